// round 14
// baseline (speedup 1.0000x reference)
#include <cuda_runtime.h>

// Problem constants (match reference_code)
#define N_USERS 200000
#define N_ITEMS 100000
#define N_NODES (N_USERS + N_ITEMS)    // 300000
#define N_EDGES 4800000
#define EMB 64
#define BATCH 4096
#define NSEL (2 * BATCH)               // 8192 selected output rows
#define BITWORDS ((N_NODES + 31) / 32) // 9375
#define BITWORDS_PAD 9376              // multiple of 4 (37.5KB)
#define CAP 128                        // bin capacity/slot (Poisson(16))
#define NVEC (N_EDGES / 4)             // 1,200,000 int4 vectors
#define QCAP 2048                      // per-block hit queue (mean ~295)
#define SCAN_BLOCKS 444                // 3 resident blocks x 148 SMs
#define VPT 6                          // int4 vectors per thread (MLP)

// Scratch (allocation-free: __device__ globals)
__device__ int      g_slot[N_NODES];             // node -> representative slot
__device__ int      g_rep[NSEL];                 // output row -> rep slot
__device__ __align__(16) unsigned g_bitmap[BITWORDS_PAD];
__device__ int      g_cnt[NSEL];                 // per-slot bin counts
__device__ __align__(16) int2 g_bin[NSEL * CAP]; // (col, val bits), 8MB
                                                 // only ever holds valid cols
                                                 // -> stale entries safe to
                                                 // gather (masked by v=0).

// L2-persistence policy: created once per thread, applied per gather via the
// cache_hint operand form (the inline evict_last modifier is v8.b32-only on
// this ptxas; the policy-operand form supports .v4.f32).
__device__ __forceinline__ unsigned long long mk_keep_policy() {
    unsigned long long pol;
    asm("createpolicy.fractional.L2::evict_last.b64 %0, 1.0;" : "=l"(pol));
    return pol;
}
__device__ __forceinline__ float4 ldg_keep(const float4* p,
                                           unsigned long long pol) {
    float4 r;
    asm("ld.global.nc.L2::cache_hint.v4.f32 {%0,%1,%2,%3}, [%4], %5;"
        : "=f"(r.x), "=f"(r.y), "=f"(r.z), "=f"(r.w)
        : "l"(p), "l"(pol));
    return r;
}

// ---------------------------------------------------------------------------
// Kernel 1: zero the membership bitmap (graph replays -> re-zero each call).
// ---------------------------------------------------------------------------
__global__ void k_init() {
    int i = blockIdx.x * blockDim.x + threadIdx.x;
    int stride = gridDim.x * blockDim.x;
    for (int t = i; t < BITWORDS_PAD; t += stride) g_bitmap[t] = 0u;
}

// ---------------------------------------------------------------------------
// Kernel 2: node->slot map + bitmap + zero this slot's bin counter.
// Duplicate ids: plain-write race picks ONE representative; any winner is
// correct (its bin holds the full edge set for that node).
// ---------------------------------------------------------------------------
__global__ void k_build(const int* __restrict__ user_id,
                        const int* __restrict__ item_id) {
    int i = blockIdx.x * blockDim.x + threadIdx.x;
    if (i >= NSEL) return;
    int node = (i < BATCH) ? user_id[i] : (N_USERS + item_id[i - BATCH]);
    g_slot[node] = i;
    g_cnt[i] = 0;
    atomicOr(&g_bitmap[node >> 5], 1u << (node & 31));
}

// ---------------------------------------------------------------------------
// Kernel 3: scan edges -> per-block SMEM hit queue -> dense drain into bins.
// Streams use __ldcs (L2 evict-first) so they don't evict the emb rows the
// gather kernel wants resident. Prologue also resolves g_rep.
// ---------------------------------------------------------------------------
__global__ void __launch_bounds__(512, 3)
k_scan(const int4*  __restrict__ adj_row4,
       const int*   __restrict__ adj_col,
       const float* __restrict__ adj_vals,
       const int*   __restrict__ user_id,
       const int*   __restrict__ item_id) {
    __shared__ __align__(16) unsigned sbm[BITWORDS_PAD];
    __shared__ int2 q[QCAP];
    __shared__ int  qn;

    const int tid = blockIdx.x * 512 + threadIdx.x;

    // merged k_rep: one entry per thread across the first 16 blocks
    if (tid < NSEL) {
        int node = (tid < BATCH) ? user_id[tid]
                                 : (N_USERS + item_id[tid - BATCH]);
        g_rep[tid] = g_slot[node];
    }

    if (threadIdx.x == 0) qn = 0;
    {
        const uint4* src = (const uint4*)g_bitmap;
        uint4*       dst = (uint4*)sbm;
        for (int t = threadIdx.x; t < BITWORDS_PAD / 4; t += 512)
            dst[t] = src[t];
    }
    __syncthreads();

    const int nthread = SCAN_BLOCKS * 512;   // 227,328

    int4 r[VPT];
    #pragma unroll
    for (int t = 0; t < VPT; t++) {
        int i = tid + t * nthread;
        if (i < NVEC) r[t] = __ldcs(&adj_row4[i]);   // evict-first stream
    }
    #pragma unroll
    for (int t = 0; t < VPT; t++) {
        int i = tid + t * nthread;
        if (i >= NVEC) break;
        int rv[4] = {r[t].x, r[t].y, r[t].z, r[t].w};
        #pragma unroll
        for (int k = 0; k < 4; k++) {
            int rn = rv[k];
            if ((sbm[rn >> 5] >> (rn & 31)) & 1u) {
                int e = 4 * i + k;
                int p = atomicAdd(&qn, 1);          // ATOMS, rare
                if (p < QCAP) {
                    q[p] = make_int2(e, rn);
                } else {                            // statistically impossible
                    int s = g_slot[rn];
                    int pos = atomicAdd(&g_cnt[s], 1);
                    if (pos < CAP)
                        g_bin[s * CAP + pos] =
                            make_int2(__ldcs(&adj_col[e]),
                                      __float_as_int(__ldcs(&adj_vals[e])));
                }
            }
        }
    }
    __syncthreads();

    int n = qn < QCAP ? qn : QCAP;
    for (int t = threadIdx.x; t < n; t += 512) {
        int2 er = q[t];
        int   c = __ldcs(&adj_col[er.x]);
        float v = __ldcs(&adj_vals[er.x]);
        int   s = g_slot[er.y];
        int pos = atomicAdd(&g_cnt[s], 1);
        if (pos < CAP)
            g_bin[s * CAP + pos] = make_int2(c, __float_as_int(v));
    }
}

// ---------------------------------------------------------------------------
// Kernel 4 (fused accum + out): one warp per OUTPUT ROW.
//  - speculative preload of first 16 bin entries || cnt || x0 row
//  - ALL 16 preloaded entries' emb gathers issued before any FMA (8 LDG.128
//    per lane in flight; 16-lane halves, edge j = 2t+half)
//  - emb gathers carry an evict_last cache policy -> L2-resident across
//    graph replays
//  - halves combined via shfl_xor(16); lanes 0-15 store out float4.
// ---------------------------------------------------------------------------
__device__ __forceinline__ const float4* emb_row(int c,
                                                 const float* __restrict__ ue,
                                                 const float* __restrict__ ie) {
    return (c < N_USERS)
        ? (const float4*)(ue + (size_t)c * EMB)
        : (const float4*)(ie + (size_t)(c - N_USERS) * EMB);
}

__global__ void __launch_bounds__(256)
k_accum_out(const float* __restrict__ user_emb,
            const float* __restrict__ item_emb,
            const int*   __restrict__ user_id,
            const int*   __restrict__ item_id,
            float4*      __restrict__ out4) {
    const int row  = (blockIdx.x * blockDim.x + threadIdx.x) >> 5;
    const int lane = threadIdx.x & 31;
    if (row >= NSEL) return;
    const int half = lane >> 4;     // which edge of a pair
    const int l16  = lane & 15;     // float4 index within emb row

    const unsigned long long pol = mk_keep_policy();

    // Level 1: independent loads
    int rep = g_rep[row];
    int id  = (row < BATCH) ? user_id[row] : item_id[row - BATCH];

    // Level 2: all independent — cnt, 16 speculative bin entries, x0 row
    const int4* bin4 = (const int4*)(g_bin + rep * CAP); // 2 entries per int4
    int4 eb[8];
    #pragma unroll
    for (int t = 0; t < 8; t++) eb[t] = bin4[t];
    int cnt = g_cnt[rep];
    if (cnt > CAP) cnt = CAP;
    const float4* x0p = (row < BATCH)
        ? (const float4*)(user_emb + (size_t)id * EMB)
        : (const float4*)(item_emb + (size_t)id * EMB);
    float4 x0 = ldg_keep(x0p + l16, pol);

    float4 acc = make_float4(0.f, 0.f, 0.f, 0.f);

    // Level 3: 8 gathers per lane in flight covering entries 0..15, then FMA.
    {
        float4 x[8];
        float  v[8];
        #pragma unroll
        for (int t = 0; t < 8; t++) {
            int j  = 2 * t + half;
            int c  = half ? eb[t].z : eb[t].x;
            int vb = half ? eb[t].w : eb[t].y;
            v[t] = (j < cnt) ? __int_as_float(vb) : 0.0f;
            // stale cols are valid node ids -> safe gather even when j>=cnt
            x[t] = ldg_keep(emb_row(c, user_emb, item_emb) + l16, pol);
        }
        #pragma unroll
        for (int t = 0; t < 8; t++) {
            acc.x += v[t] * x[t].x;
            acc.y += v[t] * x[t].y;
            acc.z += v[t] * x[t].z;
            acc.w += v[t] * x[t].w;
        }
    }

    // Tail: entries 16..cnt-1 in batches of 8 (rare; Poisson(16) tail)
    for (int j0 = 16; j0 < cnt; j0 += 8) {
        int4 b[4];
        #pragma unroll
        for (int t = 0; t < 4; t++) b[t] = bin4[j0 / 2 + t];
        float4 x[4];
        float  v[4];
        #pragma unroll
        for (int t = 0; t < 4; t++) {
            int j  = j0 + 2 * t + half;
            int c  = half ? b[t].z : b[t].x;
            int vb = half ? b[t].w : b[t].y;
            v[t] = (j < cnt) ? __int_as_float(vb) : 0.0f;
            x[t] = ldg_keep(emb_row(c, user_emb, item_emb) + l16, pol);
        }
        #pragma unroll
        for (int t = 0; t < 4; t++) {
            acc.x += v[t] * x[t].x;
            acc.y += v[t] * x[t].y;
            acc.z += v[t] * x[t].z;
            acc.w += v[t] * x[t].w;
        }
    }

    // combine the two halves (lane l and l^16 cover the same emb elems)
    acc.x += __shfl_xor_sync(0xffffffffu, acc.x, 16);
    acc.y += __shfl_xor_sync(0xffffffffu, acc.y, 16);
    acc.z += __shfl_xor_sync(0xffffffffu, acc.z, 16);
    acc.w += __shfl_xor_sync(0xffffffffu, acc.w, 16);

    if (half == 0) {
        out4[row * 16 + l16] = make_float4(2.0f * x0.x + acc.x,
                                           2.0f * x0.y + acc.y,
                                           2.0f * x0.z + acc.z,
                                           2.0f * x0.w + acc.w);
    }
}

// ---------------------------------------------------------------------------
// Inputs (metadata order): user_emb, item_emb, adj_row, adj_col, adj_vals,
//                          user_id, item_id. Output: 8192x64 float32.
// ---------------------------------------------------------------------------
extern "C" void kernel_launch(void* const* d_in, const int* in_sizes, int n_in,
                              void* d_out, int out_size) {
    const float* user_emb = (const float*)d_in[0];
    const float* item_emb = (const float*)d_in[1];
    const int4*  adj_row4 = (const int4*)d_in[2];
    const int*   adj_col  = (const int*)d_in[3];
    const float* adj_vals = (const float*)d_in[4];
    const int*   user_id  = (const int*)d_in[5];
    const int*   item_id  = (const int*)d_in[6];
    float4*      out4     = (float4*)d_out;

    k_init <<<64, 256>>>();
    k_build<<<(NSEL + 255) / 256, 256>>>(user_id, item_id);
    k_scan <<<SCAN_BLOCKS, 512>>>(adj_row4, adj_col, adj_vals,
                                  user_id, item_id);
    k_accum_out<<<NSEL / 8, 256>>>(user_emb, item_emb,
                                   user_id, item_id, out4);
}

// round 16
// speedup vs baseline: 1.0142x; 1.0142x over previous
#include <cuda_runtime.h>

// Problem constants (match reference_code)
#define N_USERS 200000
#define N_ITEMS 100000
#define N_NODES (N_USERS + N_ITEMS)    // 300000
#define N_EDGES 4800000
#define EMB 64
#define BATCH 4096
#define NSEL (2 * BATCH)               // 8192 selected output rows
#define BITWORDS ((N_NODES + 31) / 32) // 9375
#define BITWORDS_PAD 9376              // multiple of 4 (37.5KB)
#define CAP 128                        // bin capacity/slot (Poisson(16))
#define NVEC (N_EDGES / 4)             // 1,200,000 int4 vectors
#define QCAP 2048                      // per-block hit queue (mean ~295)
#define SCAN_BLOCKS 444                // 3 resident blocks x 148 SMs
#define VPT 6                          // int4 vectors per thread (MLP)

// Scratch (allocation-free: __device__ globals)
__device__ int      g_slot[N_NODES];             // node -> representative slot
__device__ int      g_rep[NSEL];                 // output row -> rep slot
__device__ __align__(16) unsigned g_bitmap[BITWORDS_PAD];
__device__ int      g_cnt[NSEL];                 // per-slot bin counts
__device__ __align__(16) int2 g_bin[NSEL * CAP]; // (col, val bits), 8MB
                                                 // only ever holds valid cols
                                                 // -> stale entries safe to
                                                 // gather (masked by v=0).

// ---------------------------------------------------------------------------
// Kernel 1: zero the membership bitmap (graph replays -> re-zero each call).
// ---------------------------------------------------------------------------
__global__ void k_init() {
    int i = blockIdx.x * blockDim.x + threadIdx.x;
    int stride = gridDim.x * blockDim.x;
    for (int t = i; t < BITWORDS_PAD; t += stride) g_bitmap[t] = 0u;
}

// ---------------------------------------------------------------------------
// Kernel 2: node->slot map + bitmap + zero this slot's bin counter.
// Duplicate ids: plain-write race picks ONE representative; any winner is
// correct (its bin holds the full edge set for that node).
// ---------------------------------------------------------------------------
__global__ void k_build(const int* __restrict__ user_id,
                        const int* __restrict__ item_id) {
    int i = blockIdx.x * blockDim.x + threadIdx.x;
    if (i >= NSEL) return;
    int node = (i < BATCH) ? user_id[i] : (N_USERS + item_id[i - BATCH]);
    g_slot[node] = i;
    g_cnt[i] = 0;
    atomicOr(&g_bitmap[node >> 5], 1u << (node & 31));
}

// ---------------------------------------------------------------------------
// Kernel 3: scan edges -> per-block SMEM hit queue -> dense drain into bins.
// Streams use __ldcs (evict-first). Prologue also resolves g_rep.
// ---------------------------------------------------------------------------
__global__ void __launch_bounds__(512, 3)
k_scan(const int4*  __restrict__ adj_row4,
       const int*   __restrict__ adj_col,
       const float* __restrict__ adj_vals,
       const int*   __restrict__ user_id,
       const int*   __restrict__ item_id) {
    __shared__ __align__(16) unsigned sbm[BITWORDS_PAD];
    __shared__ int2 q[QCAP];
    __shared__ int  qn;

    const int tid = blockIdx.x * 512 + threadIdx.x;

    // merged k_rep: one entry per thread across the first 16 blocks
    if (tid < NSEL) {
        int node = (tid < BATCH) ? user_id[tid]
                                 : (N_USERS + item_id[tid - BATCH]);
        g_rep[tid] = g_slot[node];
    }

    if (threadIdx.x == 0) qn = 0;
    {
        const uint4* src = (const uint4*)g_bitmap;
        uint4*       dst = (uint4*)sbm;
        for (int t = threadIdx.x; t < BITWORDS_PAD / 4; t += 512)
            dst[t] = src[t];
    }
    __syncthreads();

    const int nthread = SCAN_BLOCKS * 512;   // 227,328

    int4 r[VPT];
    #pragma unroll
    for (int t = 0; t < VPT; t++) {
        int i = tid + t * nthread;
        if (i < NVEC) r[t] = __ldcs(&adj_row4[i]);   // evict-first stream
    }
    #pragma unroll
    for (int t = 0; t < VPT; t++) {
        int i = tid + t * nthread;
        if (i >= NVEC) break;
        int rv[4] = {r[t].x, r[t].y, r[t].z, r[t].w};
        #pragma unroll
        for (int k = 0; k < 4; k++) {
            int rn = rv[k];
            if ((sbm[rn >> 5] >> (rn & 31)) & 1u) {
                int e = 4 * i + k;
                int p = atomicAdd(&qn, 1);          // ATOMS, rare
                if (p < QCAP) {
                    q[p] = make_int2(e, rn);
                } else {                            // statistically impossible
                    int s = g_slot[rn];
                    int pos = atomicAdd(&g_cnt[s], 1);
                    if (pos < CAP)
                        g_bin[s * CAP + pos] =
                            make_int2(__ldcs(&adj_col[e]),
                                      __float_as_int(__ldcs(&adj_vals[e])));
                }
            }
        }
    }
    __syncthreads();

    int n = qn < QCAP ? qn : QCAP;
    for (int t = threadIdx.x; t < n; t += 512) {
        int2 er = q[t];
        int   c = __ldcs(&adj_col[er.x]);
        float v = __ldcs(&adj_vals[er.x]);
        int   s = g_slot[er.y];
        int pos = atomicAdd(&g_cnt[s], 1);
        if (pos < CAP)
            g_bin[s * CAP + pos] = make_int2(c, __float_as_int(v));
    }
}

// ---------------------------------------------------------------------------
// Kernel 4 (fused accum + out): one warp per OUTPUT ROW.
// __launch_bounds__(256, 2) -> 128-reg budget so the 8 preloaded bin entries
// AND their 8 emb-row gathers per lane are ALL simultaneously live (true
// MLP 8 on the DRAM gather level). 16-lane halves each own one edge of a
// pair (float4/lane); halves combined via shfl_xor(16).
// ---------------------------------------------------------------------------
__device__ __forceinline__ const float4* emb_row(int c,
                                                 const float* __restrict__ ue,
                                                 const float* __restrict__ ie) {
    return (c < N_USERS)
        ? (const float4*)(ue + (size_t)c * EMB)
        : (const float4*)(ie + (size_t)(c - N_USERS) * EMB);
}

__global__ void __launch_bounds__(256, 2)
k_accum_out(const float* __restrict__ user_emb,
            const float* __restrict__ item_emb,
            const int*   __restrict__ user_id,
            const int*   __restrict__ item_id,
            float4*      __restrict__ out4) {
    const int row  = (blockIdx.x * blockDim.x + threadIdx.x) >> 5;
    const int lane = threadIdx.x & 31;
    if (row >= NSEL) return;
    const int half = lane >> 4;     // which edge of a pair
    const int l16  = lane & 15;     // float4 index within emb row

    // Level 1: independent loads
    int rep = __ldg(&g_rep[row]);
    int id  = (row < BATCH) ? __ldg(&user_id[row]) : __ldg(&item_id[row - BATCH]);

    // Level 2: all independent — cnt, 16 speculative bin entries, x0 row
    const int4* bin4 = (const int4*)(g_bin + rep * CAP); // 2 entries per int4
    int4 eb[8];
    #pragma unroll
    for (int t = 0; t < 8; t++) eb[t] = __ldg(&bin4[t]);
    int cnt = __ldg(&g_cnt[rep]);
    if (cnt > CAP) cnt = CAP;
    const float4* x0p = (row < BATCH)
        ? (const float4*)(user_emb + (size_t)id * EMB)
        : (const float4*)(item_emb + (size_t)id * EMB);
    float4 x0 = __ldg(x0p + l16);

    float4 acc = make_float4(0.f, 0.f, 0.f, 0.f);

    // Level 3: all 8 gathers per lane issued before any FMA (entries 0..15).
    {
        float4 x[8];
        float  v[8];
        #pragma unroll
        for (int t = 0; t < 8; t++) {
            int j  = 2 * t + half;
            int c  = half ? eb[t].z : eb[t].x;
            int vb = half ? eb[t].w : eb[t].y;
            v[t] = (j < cnt) ? __int_as_float(vb) : 0.0f;
            // stale cols are valid node ids -> safe gather even when j>=cnt
            x[t] = __ldg(emb_row(c, user_emb, item_emb) + l16);
        }
        #pragma unroll
        for (int t = 0; t < 8; t++) {
            acc.x += v[t] * x[t].x;
            acc.y += v[t] * x[t].y;
            acc.z += v[t] * x[t].z;
            acc.w += v[t] * x[t].w;
        }
    }

    // Tail: entries 16..cnt-1 in batches of 8 (Poisson(16) upper tail)
    for (int j0 = 16; j0 < cnt; j0 += 8) {
        int4 b[4];
        #pragma unroll
        for (int t = 0; t < 4; t++) b[t] = __ldg(&bin4[j0 / 2 + t]);
        float4 x[4];
        float  v[4];
        #pragma unroll
        for (int t = 0; t < 4; t++) {
            int j  = j0 + 2 * t + half;
            int c  = half ? b[t].z : b[t].x;
            int vb = half ? b[t].w : b[t].y;
            v[t] = (j < cnt) ? __int_as_float(vb) : 0.0f;
            x[t] = __ldg(emb_row(c, user_emb, item_emb) + l16);
        }
        #pragma unroll
        for (int t = 0; t < 4; t++) {
            acc.x += v[t] * x[t].x;
            acc.y += v[t] * x[t].y;
            acc.z += v[t] * x[t].z;
            acc.w += v[t] * x[t].w;
        }
    }

    // combine the two halves (lane l and l^16 cover the same emb elems)
    acc.x += __shfl_xor_sync(0xffffffffu, acc.x, 16);
    acc.y += __shfl_xor_sync(0xffffffffu, acc.y, 16);
    acc.z += __shfl_xor_sync(0xffffffffu, acc.z, 16);
    acc.w += __shfl_xor_sync(0xffffffffu, acc.w, 16);

    if (half == 0) {
        out4[row * 16 + l16] = make_float4(2.0f * x0.x + acc.x,
                                           2.0f * x0.y + acc.y,
                                           2.0f * x0.z + acc.z,
                                           2.0f * x0.w + acc.w);
    }
}

// ---------------------------------------------------------------------------
// Inputs (metadata order): user_emb, item_emb, adj_row, adj_col, adj_vals,
//                          user_id, item_id. Output: 8192x64 float32.
// ---------------------------------------------------------------------------
extern "C" void kernel_launch(void* const* d_in, const int* in_sizes, int n_in,
                              void* d_out, int out_size) {
    const float* user_emb = (const float*)d_in[0];
    const float* item_emb = (const float*)d_in[1];
    const int4*  adj_row4 = (const int4*)d_in[2];
    const int*   adj_col  = (const int*)d_in[3];
    const float* adj_vals = (const float*)d_in[4];
    const int*   user_id  = (const int*)d_in[5];
    const int*   item_id  = (const int*)d_in[6];
    float4*      out4     = (float4*)d_out;

    k_init <<<64, 256>>>();
    k_build<<<(NSEL + 255) / 256, 256>>>(user_id, item_id);
    k_scan <<<SCAN_BLOCKS, 512>>>(adj_row4, adj_col, adj_vals,
                                  user_id, item_id);
    k_accum_out<<<NSEL / 8, 256>>>(user_emb, item_emb,
                                   user_id, item_id, out4);
}